// round 14
// baseline (speedup 1.0000x reference)
#include <cuda_runtime.h>

// Problem constants (fixed by setup_inputs)
#define BB 4
#define LL 256
#define DMM 256
#define DLL 64
#define RRR 256
#define NROWS (BB*LL)        // 1024
#define KCAT 512

// ---------------------------------------------------------------------------
// Scratch (device globals — no allocation allowed)
// ---------------------------------------------------------------------------
__device__ float g_qz[NROWS * DMM];     // masked softmax(x)            (1 MB)
__device__ float g_up[128 * DMM];       // per-8-row-slab column partials of qz
__device__ float g_M [DMM * DMM];       // M[b][a] = sum_t sum_d V sW U

// ---------------------------------------------------------------------------
// Kernel 1 (fused, independent halves):
//  blocks [0,128):  warp-per-row masked softmax of x -> g_qz, plus the
//                   block's 8-row partial column sums -> g_up[blk][256]
//  blocks [128,192): M[b][a] = sum_t sum_d V[t][b][d]*sW[t,d]*U[t][a][d]
//                   NT GEMM 256x256, K=512 (t-concat); sW computed inline.
//                   32x32 tiles, 2x2 acc, double-buffered smem.
// ---------------------------------------------------------------------------
__global__ __launch_bounds__(256) void k_fused(const float* __restrict__ x,
                                               const int* __restrict__ mask,
                                               const float* __restrict__ U,
                                               const float* __restrict__ V,
                                               const float* __restrict__ W) {
    // smem pool overlaid by the two branches:
    //  softmax branch: sm[8][256]                      (2048 floats)
    //  GEMM branch:    As[2][32][34] | Bs[2][32][34] | sWs[512]  (4864 floats)
    __shared__ __align__(16) float pool[4864];
    const int tid = threadIdx.x;

    if (blockIdx.x < 128) {
        // ---------------- softmax + u-partials ----------------
        float (*sm)[256] = (float (*)[256])pool;
        const int wid = tid >> 5, lane = tid & 31;
        const int row = blockIdx.x * 8 + wid;

        const float4* xr = (const float4*)(x + row * DMM);
        float4 v0 = xr[lane];
        float4 v1 = xr[lane + 32];

        float m = fmaxf(fmaxf(fmaxf(v0.x, v0.y), fmaxf(v0.z, v0.w)),
                        fmaxf(fmaxf(v1.x, v1.y), fmaxf(v1.z, v1.w)));
        #pragma unroll
        for (int off = 16; off > 0; off >>= 1)
            m = fmaxf(m, __shfl_xor_sync(0xFFFFFFFFu, m, off));

        float4 e0 = make_float4(__expf(v0.x - m), __expf(v0.y - m),
                                __expf(v0.z - m), __expf(v0.w - m));
        float4 e1 = make_float4(__expf(v1.x - m), __expf(v1.y - m),
                                __expf(v1.z - m), __expf(v1.w - m));

        float s = e0.x + e0.y + e0.z + e0.w + e1.x + e1.y + e1.z + e1.w;
        #pragma unroll
        for (int off = 16; off > 0; off >>= 1)
            s += __shfl_xor_sync(0xFFFFFFFFu, s, off);

        float sc = (mask[row] != 0) ? (1.0f / s) : 0.0f;
        float4 q0 = make_float4(e0.x * sc, e0.y * sc, e0.z * sc, e0.w * sc);
        float4 q1 = make_float4(e1.x * sc, e1.y * sc, e1.z * sc, e1.w * sc);

        float4* qr = (float4*)(g_qz + row * DMM);
        qr[lane]      = q0;
        qr[lane + 32] = q1;

        *(float4*)&sm[wid][lane * 4]       = q0;
        *(float4*)&sm[wid][128 + lane * 4] = q1;
        __syncthreads();

        float p = 0.0f;
        #pragma unroll
        for (int w = 0; w < 8; w++) p += sm[w][tid];
        g_up[blockIdx.x * DMM + tid] = p;
        return;
    }

    // ---------------- M GEMM ----------------
    float (*As)[32][34] = (float (*)[32][34])pool;          // 2176 floats
    float (*Bs)[32][34] = (float (*)[32][34])(pool + 2176); // 2176 floats
    float* sWs = pool + 4352;                               // 512 floats

    // inline sW: thread tid -> entries tid (t=0) and 256+tid (t=1)
    {
        const float* w0 = W + tid;                 // t=0, d=tid
        const float* w1 = W + DLL * RRR + tid;     // t=1, d=tid
        float s0 = 0.0f, s1 = 0.0f;
        #pragma unroll 16
        for (int c = 0; c < DLL; c++) {
            s0 += w0[c * RRR];
            s1 += w1[c * RRR];
        }
        sWs[tid]       = s0 * (1.0f / 64.0f);
        sWs[256 + tid] = s1 * (1.0f / 64.0f);
    }
    __syncthreads();

    const int bx2 = blockIdx.x - 128;
    const int b0 = (bx2 >> 3) * 32;
    const int a0 = (bx2 & 7) * 32;

    const int kk = tid & 31, rr = tid >> 5;      // loads: +8 per p
    const int tx = tid & 15, ty = tid >> 4;      // compute: 16x16, 2x2 acc

    float acc[2][2] = {};
    float ar[4], br[4];

    // prologue kb = 0 (t = 0)
    #pragma unroll
    for (int p = 0; p < 4; p++) {
        ar[p] = V[(b0 + rr + 8 * p) * RRR + kk];
        br[p] = U[(a0 + rr + 8 * p) * RRR + kk];
    }
    #pragma unroll
    for (int p = 0; p < 4; p++) {
        As[0][kk][rr + 8 * p] = ar[p] * sWs[kk];
        Bs[0][kk][rr + 8 * p] = br[p];
    }
    __syncthreads();

    int buf = 0;
    for (int kb = 0; kb < 16; kb++) {            // K = 512 over both t
        const int kn = (kb + 1) * 32;
        if (kb < 15) {
            const float* Vn = V + (kn >> 8) * (DMM * RRR) + (kn & 255);
            const float* Un = U + (kn >> 8) * (DMM * RRR) + (kn & 255);
            #pragma unroll
            for (int p = 0; p < 4; p++) {
                ar[p] = Vn[(b0 + rr + 8 * p) * RRR + kk];
                br[p] = Un[(a0 + rr + 8 * p) * RRR + kk];
            }
        }
        #pragma unroll
        for (int k2 = 0; k2 < 32; k2++) {
            float2 a = *(const float2*)&As[buf][k2][ty * 2];
            float2 b = *(const float2*)&Bs[buf][k2][tx * 2];
            acc[0][0] = fmaf(a.x, b.x, acc[0][0]);
            acc[0][1] = fmaf(a.x, b.y, acc[0][1]);
            acc[1][0] = fmaf(a.y, b.x, acc[1][0]);
            acc[1][1] = fmaf(a.y, b.y, acc[1][1]);
        }
        if (kb < 15) {
            #pragma unroll
            for (int p = 0; p < 4; p++) {
                As[buf ^ 1][kk][rr + 8 * p] = ar[p] * sWs[kn + kk];
                Bs[buf ^ 1][kk][rr + 8 * p] = br[p];
            }
            __syncthreads();
            buf ^= 1;
        }
    }

    #pragma unroll
    for (int i = 0; i < 2; i++) {
        float2 v2 = make_float2(acc[i][0], acc[i][1]);
        *(float2*)&g_M[(b0 + ty * 2 + i) * DMM + a0 + tx * 2] = v2;
    }
}

// ---------------------------------------------------------------------------
// Kernel 2: out[row,a] = x[row,a] + valid_row * sum_k (u[z,k]-qz[row,k]) * M[k,a]
//           u[z] staged from the 32 per-slab partials g_up[z*32 .. z*32+31].
// Tiles 32(m) x 64(a), K=256 (BK=32, 8 k-blocks), 2x4 acc, double-buffered.
// Grid 128 = one wave.
// ---------------------------------------------------------------------------
__global__ __launch_bounds__(256) void k_out(const float* __restrict__ x,
                                             const int* __restrict__ mask,
                                             float* __restrict__ out) {
    __shared__ __align__(16) float As[2][32][34];   // [kk][mm], even pad
    __shared__ __align__(16) float Bs[2][32][64];   // [kk][aa]
    __shared__ float us[256];

    const int bx = blockIdx.x;
    const int m0 = (bx >> 2) * 32;
    const int a0 = (bx & 3) * 64;
    const int z  = m0 >> 8;
    const int tid = threadIdx.x;

    {
        const float* up = g_up + z * 32 * DMM + tid;
        float acc_u = 0.0f;
        #pragma unroll
        for (int s = 0; s < 32; s++) acc_u += up[s * DMM];
        us[tid] = acc_u;
    }
    __syncthreads();

    const int a_kk = tid & 31, a_mm = tid >> 5;     // A loads: +8 per p (4 ps)
    const int b_aa = tid & 63, b_kk = tid >> 6;     // B loads: +4 per p (8 ps)
    const int tx = tid & 15, ty = tid >> 4;         // compute: 2 rows x 4 cols

    float acc[2][4] = {};
    float ar[4], brM[8];

    // prologue kb = 0
    #pragma unroll
    for (int p = 0; p < 4; p++)
        ar[p] = g_qz[(m0 + a_mm + 8 * p) * DMM + a_kk];
    #pragma unroll
    for (int p = 0; p < 8; p++)
        brM[p] = g_M[(b_kk + 4 * p) * DMM + a0 + b_aa];
    #pragma unroll
    for (int p = 0; p < 4; p++)
        As[0][a_kk][a_mm + 8 * p] = us[a_kk] - ar[p];
    #pragma unroll
    for (int p = 0; p < 8; p++)
        Bs[0][b_kk + 4 * p][b_aa] = brM[p];
    __syncthreads();

    int buf = 0;
    for (int kb = 0; kb < 8; kb++) {
        const int k0n = (kb + 1) * 32;
        if (kb < 7) {
            #pragma unroll
            for (int p = 0; p < 4; p++)
                ar[p] = g_qz[(m0 + a_mm + 8 * p) * DMM + k0n + a_kk];
            #pragma unroll
            for (int p = 0; p < 8; p++)
                brM[p] = g_M[(k0n + b_kk + 4 * p) * DMM + a0 + b_aa];
        }
        #pragma unroll
        for (int k2 = 0; k2 < 32; k2++) {
            float2 a = *(const float2*)&As[buf][k2][ty * 2];
            float4 b = *(const float4*)&Bs[buf][k2][tx * 4];
            float av[2] = {a.x, a.y};
            float bv[4] = {b.x, b.y, b.z, b.w};
            #pragma unroll
            for (int i = 0; i < 2; i++)
                #pragma unroll
                for (int j = 0; j < 4; j++)
                    acc[i][j] = fmaf(av[i], bv[j], acc[i][j]);
        }
        if (kb < 7) {
            #pragma unroll
            for (int p = 0; p < 4; p++)
                As[buf ^ 1][a_kk][a_mm + 8 * p] = us[k0n + a_kk] - ar[p];
            #pragma unroll
            for (int p = 0; p < 8; p++)
                Bs[buf ^ 1][b_kk + 4 * p][b_aa] = brM[p];
            __syncthreads();
            buf ^= 1;
        }
    }

    #pragma unroll
    for (int i = 0; i < 2; i++) {
        int row = m0 + ty * 2 + i;
        float mv = (mask[row] != 0) ? 1.0f : 0.0f;
        float4 xv = *(const float4*)&x[row * DMM + a0 + tx * 4];
        float4 ov = make_float4(fmaf(mv, acc[i][0], xv.x),
                                fmaf(mv, acc[i][1], xv.y),
                                fmaf(mv, acc[i][2], xv.z),
                                fmaf(mv, acc[i][3], xv.w));
        *(float4*)&out[row * DMM + a0 + tx * 4] = ov;
    }
}

// ---------------------------------------------------------------------------
// Launch
// Inputs (metadata order): x (f32, 262144), U (f32, 131072), V (f32, 131072),
//                          W (f32, 32768),  mask (i32, 1024)
// ---------------------------------------------------------------------------
extern "C" void kernel_launch(void* const* d_in, const int* in_sizes, int n_in,
                              void* d_out, int out_size) {
    (void)in_sizes; (void)n_in; (void)out_size;
    const float* x    = (const float*)d_in[0];
    const float* U    = (const float*)d_in[1];
    const float* V    = (const float*)d_in[2];
    const float* W    = (const float*)d_in[3];
    const int*   mask = (const int*)d_in[4];
    float* out = (float*)d_out;

    k_fused<<<192, 256>>>(x, mask, U, V, W);
    k_out<<<128, 256>>>(x, mask, out);
}

// round 15
// speedup vs baseline: 1.4437x; 1.4437x over previous
#include <cuda_runtime.h>

// Problem constants (fixed by setup_inputs)
#define BB 4
#define LL 256
#define DMM 256
#define DLL 64
#define RRR 256
#define NROWS (BB*LL)        // 1024

// ---------------------------------------------------------------------------
// Scratch (device globals — no allocation allowed)
// ---------------------------------------------------------------------------
__device__ float g_qz[NROWS * DMM];     // masked softmax(x)            (1 MB)
__device__ float g_up[128 * DMM];       // per-8-row-slab column partials
__device__ float g_Mp[2 * DMM * DMM];   // Mp[t][b][a]; M = Mp[0]+Mp[1]
__device__ unsigned int g_bar;          // grid barrier counter (zero-init;
                                        // generation-based, never reset)

// ---------------------------------------------------------------------------
// Single fused kernel, grid 128 x 256 threads (all blocks co-resident).
// Phase 1a: block bx -> softmax rows [bx*8, bx*8+8) + column partial g_up[bx]
// Phase 1b: block bx -> Mp tile (t = bx>>6, b0 = ((bx>>3)&7)*32, a0=(bx&7)*32),
//           K=256, sW inline, 2x2 acc, double-buffered smem
// Barrier:  threadfence + atomic generation counter + volatile poll
// Phase 2:  block bx -> out tile (m0=(bx>>2)*32, a0=(bx&3)*64), K=256,
//           A = u[z]-qz staged on the fly, B = Mp0+Mp1, 2x4 acc, dbuf
// ---------------------------------------------------------------------------
__global__ __launch_bounds__(256) void k_all(const float* __restrict__ x,
                                             const int* __restrict__ mask,
                                             const float* __restrict__ U,
                                             const float* __restrict__ V,
                                             const float* __restrict__ W,
                                             float* __restrict__ out) {
    // smem pool overlaid by phases:
    //  1a: sm[8][256]                          (2048 floats)
    //  1b: As[2][32][34] Bs[2][32][34] sWs[256] (4608 floats)
    //  2 : As2[2][32][34] Bs2[2][32][64] us[256] (6528 floats)
    __shared__ __align__(16) float pool[6528];
    const int tid = threadIdx.x;
    const int bx  = blockIdx.x;

    // ================= Phase 1a: softmax + u-partials =================
    {
        float (*sm)[256] = (float (*)[256])pool;
        const int wid = tid >> 5, lane = tid & 31;
        const int row = bx * 8 + wid;

        const float4* xr = (const float4*)(x + row * DMM);
        float4 v0 = xr[lane];
        float4 v1 = xr[lane + 32];

        float m = fmaxf(fmaxf(fmaxf(v0.x, v0.y), fmaxf(v0.z, v0.w)),
                        fmaxf(fmaxf(v1.x, v1.y), fmaxf(v1.z, v1.w)));
        #pragma unroll
        for (int off = 16; off > 0; off >>= 1)
            m = fmaxf(m, __shfl_xor_sync(0xFFFFFFFFu, m, off));

        float4 e0 = make_float4(__expf(v0.x - m), __expf(v0.y - m),
                                __expf(v0.z - m), __expf(v0.w - m));
        float4 e1 = make_float4(__expf(v1.x - m), __expf(v1.y - m),
                                __expf(v1.z - m), __expf(v1.w - m));

        float s = e0.x + e0.y + e0.z + e0.w + e1.x + e1.y + e1.z + e1.w;
        #pragma unroll
        for (int off = 16; off > 0; off >>= 1)
            s += __shfl_xor_sync(0xFFFFFFFFu, s, off);

        float sc = (mask[row] != 0) ? (1.0f / s) : 0.0f;
        float4 q0 = make_float4(e0.x * sc, e0.y * sc, e0.z * sc, e0.w * sc);
        float4 q1 = make_float4(e1.x * sc, e1.y * sc, e1.z * sc, e1.w * sc);

        float4* qr = (float4*)(g_qz + row * DMM);
        qr[lane]      = q0;
        qr[lane + 32] = q1;

        *(float4*)&sm[wid][lane * 4]       = q0;
        *(float4*)&sm[wid][128 + lane * 4] = q1;
        __syncthreads();

        float p = 0.0f;
        #pragma unroll
        for (int w = 0; w < 8; w++) p += sm[w][tid];
        g_up[bx * DMM + tid] = p;
    }
    __syncthreads();   // pool reuse

    // ================= Phase 1b: Mp tile (K=256, own t) =================
    {
        float (*As)[32][34] = (float (*)[32][34])pool;          // 2176
        float (*Bs)[32][34] = (float (*)[32][34])(pool + 2176); // 2176
        float* sWs = pool + 4352;                               // 256

        const int t  = bx >> 6;
        const int b0 = ((bx >> 3) & 7) * 32;
        const int a0 = (bx & 7) * 32;
        const float* Vt = V + t * (DMM * RRR);
        const float* Ut = U + t * (DMM * RRR);

        {   // inline sW for this t: sWs[d] = (1/64) * sum_c W[t][c][d]
            const float* w = W + t * DLL * RRR + tid;
            float s0 = 0.0f;
            #pragma unroll 16
            for (int c = 0; c < DLL; c++) s0 += w[c * RRR];
            sWs[tid] = s0 * (1.0f / 64.0f);
        }
        __syncthreads();

        const int kk = tid & 31, rr = tid >> 5;      // loads: +8 per p
        const int tx = tid & 15, ty = tid >> 4;      // compute: 16x16, 2x2

        float acc[2][2] = {};
        float ar[4], br[4];

        #pragma unroll
        for (int p = 0; p < 4; p++) {
            ar[p] = Vt[(b0 + rr + 8 * p) * RRR + kk];
            br[p] = Ut[(a0 + rr + 8 * p) * RRR + kk];
        }
        #pragma unroll
        for (int p = 0; p < 4; p++) {
            As[0][kk][rr + 8 * p] = ar[p] * sWs[kk];
            Bs[0][kk][rr + 8 * p] = br[p];
        }
        __syncthreads();

        int buf = 0;
        for (int kb = 0; kb < 8; kb++) {
            const int kn = (kb + 1) * 32;
            if (kb < 7) {
                #pragma unroll
                for (int p = 0; p < 4; p++) {
                    ar[p] = Vt[(b0 + rr + 8 * p) * RRR + kn + kk];
                    br[p] = Ut[(a0 + rr + 8 * p) * RRR + kn + kk];
                }
            }
            #pragma unroll
            for (int k2 = 0; k2 < 32; k2++) {
                float2 a = *(const float2*)&As[buf][k2][ty * 2];
                float2 b = *(const float2*)&Bs[buf][k2][tx * 2];
                acc[0][0] = fmaf(a.x, b.x, acc[0][0]);
                acc[0][1] = fmaf(a.x, b.y, acc[0][1]);
                acc[1][0] = fmaf(a.y, b.x, acc[1][0]);
                acc[1][1] = fmaf(a.y, b.y, acc[1][1]);
            }
            if (kb < 7) {
                #pragma unroll
                for (int p = 0; p < 4; p++) {
                    As[buf ^ 1][kk][rr + 8 * p] = ar[p] * sWs[kn + kk];
                    Bs[buf ^ 1][kk][rr + 8 * p] = br[p];
                }
                __syncthreads();
                buf ^= 1;
            }
        }

        #pragma unroll
        for (int i = 0; i < 2; i++) {
            float2 v2 = make_float2(acc[i][0], acc[i][1]);
            *(float2*)&g_Mp[t * (DMM * DMM) + (b0 + ty * 2 + i) * DMM + a0 + tx * 2] = v2;
        }
    }

    // ================= grid barrier =================
    __threadfence();
    __syncthreads();
    if (tid == 0) {
        unsigned old = atomicAdd(&g_bar, 1u);
        unsigned target = (old & ~127u) + 128u;   // counter is a multiple of
        volatile unsigned* vb = &g_bar;           // 128 at every run start
        while (*vb < target) { }
    }
    __syncthreads();
    __threadfence();

    // ================= Phase 2: out GEMM =================
    {
        float (*As2)[32][34] = (float (*)[32][34])pool;           // 2176
        float (*Bs2)[32][64] = (float (*)[32][64])(pool + 2176);  // 4096
        float* us = pool + 6272;                                  // 256

        const int m0 = (bx >> 2) * 32;
        const int a0 = (bx & 3) * 64;
        const int z  = m0 >> 8;

        {
            const float* up = g_up + z * 32 * DMM + tid;
            float au = 0.0f;
            #pragma unroll
            for (int s = 0; s < 32; s++) au += up[s * DMM];
            us[tid] = au;
        }
        __syncthreads();

        const int a_kk = tid & 31, a_mm = tid >> 5;  // A: +8 per p (4 ps)
        const int b_aa = tid & 63, b_kk = tid >> 6;  // B: +4 per p (8 ps)
        const int tx = tid & 15, ty = tid >> 4;      // 2 rows x 4 cols

        float acc[2][4] = {};
        float ar[4], brA[8], brB[8];

        #pragma unroll
        for (int p = 0; p < 4; p++)
            ar[p] = g_qz[(m0 + a_mm + 8 * p) * DMM + a_kk];
        #pragma unroll
        for (int p = 0; p < 8; p++) {
            int idx = (b_kk + 4 * p) * DMM + a0 + b_aa;
            brA[p] = g_Mp[idx];
            brB[p] = g_Mp[idx + DMM * DMM];
        }
        #pragma unroll
        for (int p = 0; p < 4; p++)
            As2[0][a_kk][a_mm + 8 * p] = us[a_kk] - ar[p];
        #pragma unroll
        for (int p = 0; p < 8; p++)
            Bs2[0][b_kk + 4 * p][b_aa] = brA[p] + brB[p];
        __syncthreads();

        int buf = 0;
        for (int kb = 0; kb < 8; kb++) {
            const int kn = (kb + 1) * 32;
            if (kb < 7) {
                #pragma unroll
                for (int p = 0; p < 4; p++)
                    ar[p] = g_qz[(m0 + a_mm + 8 * p) * DMM + kn + a_kk];
                #pragma unroll
                for (int p = 0; p < 8; p++) {
                    int idx = (kn + b_kk + 4 * p) * DMM + a0 + b_aa;
                    brA[p] = g_Mp[idx];
                    brB[p] = g_Mp[idx + DMM * DMM];
                }
            }
            #pragma unroll
            for (int k2 = 0; k2 < 32; k2++) {
                float2 a = *(const float2*)&As2[buf][k2][ty * 2];
                float4 b = *(const float4*)&Bs2[buf][k2][tx * 4];
                float av[2] = {a.x, a.y};
                float bv[4] = {b.x, b.y, b.z, b.w};
                #pragma unroll
                for (int i = 0; i < 2; i++)
                    #pragma unroll
                    for (int j = 0; j < 4; j++)
                        acc[i][j] = fmaf(av[i], bv[j], acc[i][j]);
            }
            if (kb < 7) {
                #pragma unroll
                for (int p = 0; p < 4; p++)
                    As2[buf ^ 1][a_kk][a_mm + 8 * p] = us[kn + a_kk] - ar[p];
                #pragma unroll
                for (int p = 0; p < 8; p++)
                    Bs2[buf ^ 1][b_kk + 4 * p][b_aa] = brA[p] + brB[p];
                __syncthreads();
                buf ^= 1;
            }
        }

        #pragma unroll
        for (int i = 0; i < 2; i++) {
            int row = m0 + ty * 2 + i;
            float mv = (mask[row] != 0) ? 1.0f : 0.0f;
            float4 xv = *(const float4*)&x[row * DMM + a0 + tx * 4];
            float4 ov = make_float4(fmaf(mv, acc[i][0], xv.x),
                                    fmaf(mv, acc[i][1], xv.y),
                                    fmaf(mv, acc[i][2], xv.z),
                                    fmaf(mv, acc[i][3], xv.w));
            *(float4*)&out[row * DMM + a0 + tx * 4] = ov;
        }
    }
}

// ---------------------------------------------------------------------------
// Launch — a single kernel node.
// Inputs (metadata order): x (f32, 262144), U (f32, 131072), V (f32, 131072),
//                          W (f32, 32768),  mask (i32, 1024)
// ---------------------------------------------------------------------------
extern "C" void kernel_launch(void* const* d_in, const int* in_sizes, int n_in,
                              void* d_out, int out_size) {
    (void)in_sizes; (void)n_in; (void)out_size;
    const float* x    = (const float*)d_in[0];
    const float* U    = (const float*)d_in[1];
    const float* V    = (const float*)d_in[2];
    const float* W    = (const float*)d_in[3];
    const int*   mask = (const int*)d_in[4];
    float* out = (float*)d_out;

    k_all<<<128, 256>>>(x, mask, U, V, W, out);
}